// round 9
// baseline (speedup 1.0000x reference)
#include <cuda_runtime.h>
#include <cuda_bf16.h>
#include <stdint.h>
#include <math.h>

#define N_NODESC 100000
#define N_EDGESC 1600000
#define F_INC    256
#define SCAN_BLKS ((N_NODESC + 1023) / 1024)   // 98

// ---------------- scratch (static device globals: no allocation) ----------------
__device__ float g_p1[N_NODESC * 64];   // x @ [W1l | W1r]
__device__ float g_h [N_NODESC * 32];   // relu(layer1)
__device__ int   g_deg[N_NODESC];
__device__ int   g_pos[N_NODESC];
__device__ int   g_off[N_NODESC];       // block-local exclusive scan of deg
__device__ int   g_bsum[128];
__device__ int   g_boff[128];           // exclusive scan of block sums
__device__ int   g_csr[N_EDGESC];
__device__ int   g_tick;                // last-block ticket (reset each run)

// ---------------- packed f32x2 helpers (Blackwell) ----------------
__device__ __forceinline__ unsigned long long ffma2(unsigned long long a, unsigned long long b,
                                                    unsigned long long c) {
    unsigned long long d;
    asm("fma.rn.f32x2 %0, %1, %2, %3;" : "=l"(d) : "l"(a), "l"(b), "l"(c));
    return d;
}

__device__ __forceinline__ uint32_t smem_u32(const void* p) {
    uint32_t a;
    asm("{ .reg .u64 t; cvta.to.shared.u64 t, %1; cvt.u32.u64 %0, t; }" : "=r"(a) : "l"(p));
    return a;
}

// ---------------- CSR build ----------------
__global__ void k_zero() {
    int i = blockIdx.x * blockDim.x + threadIdx.x;
    if (i < N_NODESC) { g_deg[i] = 0; g_pos[i] = 0; }
}

__global__ void k_deg(const int* __restrict__ ei) {
    int i = blockIdx.x * blockDim.x + threadIdx.x;
    if (i < N_EDGESC / 4) {
        int4 d4 = ((const int4*)(ei + N_EDGESC))[i];
        if ((unsigned)d4.x < (unsigned)N_NODESC) atomicAdd(&g_deg[d4.x], 1);
        if ((unsigned)d4.y < (unsigned)N_NODESC) atomicAdd(&g_deg[d4.y], 1);
        if ((unsigned)d4.z < (unsigned)N_NODESC) atomicAdd(&g_deg[d4.z], 1);
        if ((unsigned)d4.w < (unsigned)N_NODESC) atomicAdd(&g_deg[d4.w], 1);
    }
}

__device__ __forceinline__ int warp_iscan(int v) {
    #pragma unroll
    for (int o = 1; o < 32; o <<= 1) {
        int t = __shfl_up_sync(0xffffffffu, v, o);
        if ((threadIdx.x & 31) >= o) v += t;
    }
    return v;
}

__global__ void k_scanF() {
    __shared__ int ws[32];
    __shared__ bool lastf;
    int i = blockIdx.x * 1024 + threadIdx.x;
    int v = (i < N_NODESC) ? g_deg[i] : 0;
    int inc = warp_iscan(v);
    int wid = threadIdx.x >> 5, lane = threadIdx.x & 31;
    if (lane == 31) ws[wid] = inc;
    __syncthreads();
    if (wid == 0) {
        int wv = ws[lane];
        int wi = warp_iscan(wv);
        ws[lane] = wi - wv;
    }
    __syncthreads();
    int excl = inc - v + ws[wid];
    if (i < N_NODESC) g_off[i] = excl;
    if (threadIdx.x == 1023) g_bsum[blockIdx.x] = excl + v;

    __threadfence();
    if (threadIdx.x == 0) lastf = (atomicAdd(&g_tick, 1) == gridDim.x - 1);
    __syncthreads();
    if (lastf && threadIdx.x < 32) {
        int run = 0;
        #pragma unroll
        for (int c = 0; c < 4; c++) {
            int idx = c * 32 + lane;
            int bv = (idx < SCAN_BLKS) ? g_bsum[idx] : 0;
            int binc = warp_iscan(bv);
            if (idx < SCAN_BLKS) g_boff[idx] = run + binc - bv;
            run += __shfl_sync(0xffffffffu, binc, 31);
        }
        if (lane == 0) g_tick = 0;
    }
}

__device__ __forceinline__ int abs_off(int node) {
    return g_off[node] + g_boff[node >> 10];
}

__global__ void k_fill(const int* __restrict__ ei) {
    int i = blockIdx.x * blockDim.x + threadIdx.x;
    if (i < N_EDGESC / 4) {
        int4 s4 = ((const int4*)ei)[i];
        int4 d4 = ((const int4*)(ei + N_EDGESC))[i];
        int s[4] = {s4.x, s4.y, s4.z, s4.w};
        int d[4] = {d4.x, d4.y, d4.z, d4.w};
        #pragma unroll
        for (int j = 0; j < 4; j++) {
            if ((unsigned)d[j] < (unsigned)N_NODESC && (unsigned)s[j] < (unsigned)N_NODESC) {
                int p = atomicAdd(&g_pos[d[j]], 1);
                g_csr[abs_off(d[j]) + p] = s[j];
            }
        }
    }
}

// ---------------- GEMM1 (HMMA bf16 split): p1 = x @ [W1l|W1r] ----------------
// CTA: 128 rows x 64 cols x K=256. SMEM bf16 tiles, row = 264 elems (528B pad
// -> ldmatrix conflict-free). 3 products: Xh*Wh + Xh*Wl + Xl*Wh (fp32 accum).
// mma.sync.m16n8k16 + ldmatrix are base sm_80+ ISA (valid under compute_103).
#define G1_RS   528                         // row stride bytes (264 bf16)
#define SM_XH   0
#define SM_XL   (128 * G1_RS)               // 67584
#define SM_WH   (2 * 128 * G1_RS)           // 135168
#define SM_WL   (2 * 128 * G1_RS + 64 * G1_RS)
#define G1_SMEM (2 * 128 * G1_RS + 2 * 64 * G1_RS)   // 202752

__device__ __forceinline__ uint32_t bpack(__nv_bfloat16 a, __nv_bfloat16 b) {
    return (uint32_t)__bfloat16_as_ushort(a) | ((uint32_t)__bfloat16_as_ushort(b) << 16);
}

__device__ __forceinline__ void ldm_x4(uint32_t* r, uint32_t addr) {
    asm volatile("ldmatrix.sync.aligned.m8n8.x4.shared.b16 {%0,%1,%2,%3}, [%4];"
                 : "=r"(r[0]), "=r"(r[1]), "=r"(r[2]), "=r"(r[3]) : "r"(addr));
}

__device__ __forceinline__ void mma16816(float* c, const uint32_t* a, uint32_t b0, uint32_t b1) {
    asm volatile(
        "mma.sync.aligned.m16n8k16.row.col.f32.bf16.bf16.f32 "
        "{%0,%1,%2,%3}, {%4,%5,%6,%7}, {%8,%9}, {%0,%1,%2,%3};"
        : "+f"(c[0]), "+f"(c[1]), "+f"(c[2]), "+f"(c[3])
        : "r"(a[0]), "r"(a[1]), "r"(a[2]), "r"(a[3]), "r"(b0), "r"(b1));
}

__global__ void __launch_bounds__(256, 1) k_gemm1(const float* __restrict__ x,
                                                  const float* __restrict__ W1l,
                                                  const float* __restrict__ W1r) {
    extern __shared__ char smem[];
    uint32_t sb = smem_u32(smem);
    int tid = threadIdx.x, wid = tid >> 5, lane = tid & 31;
    int mbase = blockIdx.x * 128;

    // ---- load + split W into Wh/Wl [n=64][k=256] bf16
    #pragma unroll 4
    for (int it = 0; it < 16; it++) {
        int idx = it * 256 + tid;
        int n = idx >> 6;
        int k0 = (idx & 63) * 4;
        float v[4];
        #pragma unroll
        for (int j = 0; j < 4; j++) {
            int k = k0 + j;
            v[j] = (n < 32) ? W1l[k * 32 + n] : W1r[k * 32 + (n - 32)];
        }
        __nv_bfloat16 h[4], l[4];
        #pragma unroll
        for (int j = 0; j < 4; j++) {
            h[j] = __float2bfloat16_rn(v[j]);
            l[j] = __float2bfloat16_rn(v[j] - __bfloat162float(h[j]));
        }
        uint32_t off = n * G1_RS + k0 * 2;
        *(uint2*)(smem + SM_WH + off) = make_uint2(bpack(h[0], h[1]), bpack(h[2], h[3]));
        *(uint2*)(smem + SM_WL + off) = make_uint2(bpack(l[0], l[1]), bpack(l[2], l[3]));
    }

    // ---- load + split X into Xh/Xl [r=128][k=256] bf16
    #pragma unroll 4
    for (int it = 0; it < 32; it++) {
        int idx = it * 256 + tid;
        int r = idx >> 6;
        int k0 = (idx & 63) * 4;
        int node = mbase + r;
        float4 v = (node < N_NODESC) ? *(const float4*)(x + (size_t)node * F_INC + k0)
                                     : make_float4(0.f, 0.f, 0.f, 0.f);
        float vv[4] = {v.x, v.y, v.z, v.w};
        __nv_bfloat16 h[4], l[4];
        #pragma unroll
        for (int j = 0; j < 4; j++) {
            h[j] = __float2bfloat16_rn(vv[j]);
            l[j] = __float2bfloat16_rn(vv[j] - __bfloat162float(h[j]));
        }
        uint32_t off = r * G1_RS + k0 * 2;
        *(uint2*)(smem + SM_XH + off) = make_uint2(bpack(h[0], h[1]), bpack(h[2], h[3]));
        *(uint2*)(smem + SM_XL + off) = make_uint2(bpack(l[0], l[1]), bpack(l[2], l[3]));
    }
    __syncthreads();

    // ---- compute: warp w owns rows w*16..w*16+15, all 64 cols
    float C[8][4];
    #pragma unroll
    for (int j = 0; j < 8; j++)
        #pragma unroll
        for (int i = 0; i < 4; i++) C[j][i] = 0.f;

    // A ldmatrix address: rows (lane&15), k-half (lane>>4)
    uint32_t a_row = wid * 16 + (lane & 15);
    uint32_t a_half = (lane >> 4) * 16;
    uint32_t aH_base = sb + SM_XH + a_row * G1_RS + a_half;
    uint32_t aL_base = sb + SM_XL + a_row * G1_RS + a_half;
    // B ldmatrix address: n-row (lane&7) + ((lane>>4)<<3), k-half ((lane>>3)&1)
    uint32_t b_row = (lane & 7) + ((lane >> 4) << 3);
    uint32_t b_half = ((lane >> 3) & 1) * 16;
    uint32_t bH_base = sb + SM_WH + b_row * G1_RS + b_half;
    uint32_t bL_base = sb + SM_WL + b_row * G1_RS + b_half;

    #pragma unroll 4
    for (int ks = 0; ks < 16; ks++) {
        uint32_t koff = ks * 32;
        uint32_t Ah[4], Al[4];
        ldm_x4(Ah, aH_base + koff);
        ldm_x4(Al, aL_base + koff);
        #pragma unroll
        for (int nt = 0; nt < 4; nt++) {
            uint32_t Bh[4], Bl[4];
            ldm_x4(Bh, bH_base + nt * (16 * G1_RS) + koff);
            ldm_x4(Bl, bL_base + nt * (16 * G1_RS) + koff);
            mma16816(C[2 * nt],     Ah, Bh[0], Bh[1]);
            mma16816(C[2 * nt + 1], Ah, Bh[2], Bh[3]);
            mma16816(C[2 * nt],     Ah, Bl[0], Bl[1]);
            mma16816(C[2 * nt + 1], Ah, Bl[2], Bl[3]);
            mma16816(C[2 * nt],     Al, Bh[0], Bh[1]);
            mma16816(C[2 * nt + 1], Al, Bh[2], Bh[3]);
        }
    }

    // ---- epilogue: C fragment -> g_p1. lane l: rows w*16 + l/4 (+8), cols (l&3)*2 (+1)
    int row0 = wid * 16 + (lane >> 2);
    int cb = (lane & 3) * 2;
    int n0 = mbase + row0;
    int n1 = n0 + 8;
    #pragma unroll
    for (int j = 0; j < 8; j++) {
        int col = (j >> 1) * 16 + (j & 1) * 8 + cb;
        if (n0 < N_NODESC) *(float2*)&g_p1[(size_t)n0 * 64 + col] = make_float2(C[j][0], C[j][1]);
        if (n1 < N_NODESC) *(float2*)&g_p1[(size_t)n1 * 64 + col] = make_float2(C[j][2], C[j][3]);
    }
}

// ---------------- agg1 + combine + relu: warp per node, MLP 8 ----------------
__global__ void __launch_bounds__(256) k_agg1(const float* __restrict__ b1) {
    int w = (blockIdx.x * 256 + threadIdx.x) >> 5;
    int lane = threadIdx.x & 31;
    int deg = g_deg[w];
    int beg = abs_off(w);
    int end = beg + deg;
    float a0 = 0.f, a1 = 0.f, a2 = 0.f, a3 = 0.f;
    int e = beg;
    int e8 = beg + (deg & ~7);
    for (; e < e8; e += 8) {
        int s0 = g_csr[e],     s1 = g_csr[e + 1], s2 = g_csr[e + 2], s3 = g_csr[e + 3];
        int s4 = g_csr[e + 4], s5 = g_csr[e + 5], s6 = g_csr[e + 6], s7 = g_csr[e + 7];
        a0 += g_p1[s0 * 64 + lane];
        a1 += g_p1[s1 * 64 + lane];
        a2 += g_p1[s2 * 64 + lane];
        a3 += g_p1[s3 * 64 + lane];
        a0 += g_p1[s4 * 64 + lane];
        a1 += g_p1[s5 * 64 + lane];
        a2 += g_p1[s6 * 64 + lane];
        a3 += g_p1[s7 * 64 + lane];
    }
    for (; e < end; e++) a0 += g_p1[g_csr[e] * 64 + lane];
    float acc = (a0 + a1) + (a2 + a3);
    float invd = 1.f / fmaxf((float)deg, 1.f);
    float v = acc * invd + g_p1[w * 64 + 32 + lane] + b1[lane];
    g_h[w * 32 + lane] = fmaxf(v, 0.f);
}

// ---------------- final: gather-mean h + [W2l|W2r] matvec + log_softmax ----------------
__global__ void __launch_bounds__(256) k_final(const float* __restrict__ W2l,
                                               const float* __restrict__ W2r,
                                               const float* __restrict__ b2,
                                               float* __restrict__ out) {
    __shared__ float vs[32 * 68];
    __shared__ float Wt[40 * 68];
    __shared__ float b2s[40];
    int tid = threadIdx.x;

    for (int idx = tid; idx < 40 * 64; idx += 256) {
        int c = idx >> 6, k = idx & 63;
        Wt[c * 68 + k] = (k < 32) ? W2l[k * 40 + c] : W2r[(k - 32) * 40 + c];
    }
    if (tid < 40) b2s[tid] = b2[tid];

    int base = blockIdx.x * 32;
    int wid = tid >> 5, lane = tid & 31;

    #pragma unroll
    for (int j = 0; j < 4; j++) {
        int ln = wid * 4 + j;
        int g = base + ln;
        int deg = g_deg[g];
        int beg = abs_off(g);
        int end = beg + deg;
        float a0 = 0.f, a1 = 0.f, a2 = 0.f, a3 = 0.f;
        int e = beg;
        int e8 = beg + (deg & ~7);
        for (; e < e8; e += 8) {
            int s0 = g_csr[e],     s1 = g_csr[e + 1], s2 = g_csr[e + 2], s3 = g_csr[e + 3];
            int s4 = g_csr[e + 4], s5 = g_csr[e + 5], s6 = g_csr[e + 6], s7 = g_csr[e + 7];
            a0 += g_h[s0 * 32 + lane];
            a1 += g_h[s1 * 32 + lane];
            a2 += g_h[s2 * 32 + lane];
            a3 += g_h[s3 * 32 + lane];
            a0 += g_h[s4 * 32 + lane];
            a1 += g_h[s5 * 32 + lane];
            a2 += g_h[s6 * 32 + lane];
            a3 += g_h[s7 * 32 + lane];
        }
        for (; e < end; e++) a0 += g_h[g_csr[e] * 32 + lane];
        float acc = (a0 + a1) + (a2 + a3);
        float invd = 1.f / fmaxf((float)deg, 1.f);
        vs[ln * 68 + lane] = acc * invd;
        vs[ln * 68 + 32 + lane] = g_h[g * 32 + lane];
    }
    __syncthreads();

    int node = tid >> 3, sub = tid & 7, c0 = sub * 5;
    unsigned long long acc[5];
    #pragma unroll
    for (int j = 0; j < 5; j++) acc[j] = 0ull;
    #pragma unroll
    for (int kk = 0; kk < 64; kk += 4) {
        ulonglong2 v = *(const ulonglong2*)&vs[node * 68 + kk];
        #pragma unroll
        for (int j = 0; j < 5; j++) {
            ulonglong2 w = *(const ulonglong2*)&Wt[(c0 + j) * 68 + kk];
            acc[j] = ffma2(v.x, w.x, acc[j]);
            acc[j] = ffma2(v.y, w.y, acc[j]);
        }
    }
    float z[5];
    #pragma unroll
    for (int j = 0; j < 5; j++)
        z[j] = __uint_as_float((unsigned)acc[j]) +
               __uint_as_float((unsigned)(acc[j] >> 32)) + b2s[c0 + j];

    float m = z[0];
    #pragma unroll
    for (int j = 1; j < 5; j++) m = fmaxf(m, z[j]);
    #pragma unroll
    for (int o = 1; o < 8; o <<= 1) m = fmaxf(m, __shfl_xor_sync(0xffffffffu, m, o));
    float s = 0.f;
    #pragma unroll
    for (int j = 0; j < 5; j++) s += expf(z[j] - m);
    #pragma unroll
    for (int o = 1; o < 8; o <<= 1) s += __shfl_xor_sync(0xffffffffu, s, o);
    float ls = logf(s);

    int g = base + node;
    #pragma unroll
    for (int j = 0; j < 5; j++) out[g * 40 + c0 + j] = z[j] - m - ls;
}

// ---------------- launch: gemm1 forked, submitted 4th (ncu capture target) ----------------
extern "C" void kernel_launch(void* const* d_in, const int* in_sizes, int n_in,
                              void* d_out, int out_size) {
    const float* x   = (const float*)d_in[0];
    const int*   ei  = (const int*)d_in[1];     // int32 (JAX x64 disabled)
    const float* W1l = (const float*)d_in[2];
    const float* W1r = (const float*)d_in[3];
    const float* b1  = (const float*)d_in[4];
    const float* W2l = (const float*)d_in[5];
    const float* W2r = (const float*)d_in[6];
    const float* b2  = (const float*)d_in[7];
    float* out = (float*)d_out;

    static cudaStream_t s1 = nullptr;
    static cudaEvent_t evf = nullptr, evj = nullptr;
    if (s1 == nullptr) {
        cudaStreamCreateWithFlags(&s1, cudaStreamNonBlocking);
        cudaEventCreateWithFlags(&evf, cudaEventDisableTiming);
        cudaEventCreateWithFlags(&evj, cudaEventDisableTiming);
        cudaFuncSetAttribute(k_gemm1, cudaFuncAttributeMaxDynamicSharedMemorySize, G1_SMEM);
    }

    // fork point recorded before CSR chain; gemm1 runs concurrent with it
    cudaEventRecord(evf, 0);
    cudaStreamWaitEvent(s1, evf, 0);

    // CSR build on the main (capture) stream
    k_zero<<<(N_NODESC + 511) / 512, 512>>>();                     // launch 1
    k_deg<<<(N_EDGESC / 4 + 255) / 256, 256>>>(ei);                // launch 2
    k_scanF<<<SCAN_BLKS, 1024>>>();                                // launch 3

    k_gemm1<<<(N_NODESC + 127) / 128, 256, G1_SMEM, s1>>>(x, W1l, W1r);  // launch 4 (profiled)
    cudaEventRecord(evj, s1);

    k_fill<<<(N_EDGESC / 4 + 255) / 256, 256>>>(ei);               // launch 5

    // join, then layer 1 aggregation and fused layer 2
    cudaStreamWaitEvent(0, evj, 0);
    k_agg1<<<N_NODESC / 8, 256>>>(b1);                             // launch 6
    k_final<<<N_NODESC / 32, 256>>>(W2l, W2r, b2, out);            // launch 7
}

// round 10
// speedup vs baseline: 1.3205x; 1.3205x over previous
#include <cuda_runtime.h>
#include <cuda_bf16.h>
#include <stdint.h>
#include <math.h>

#define N_NODESC 100000
#define N_EDGESC 1600000
#define F_INC    256
#define SCAN_BLKS ((N_NODESC + 1023) / 1024)   // 98

// ---------------- scratch (static device globals: no allocation) ----------------
__device__ float g_p1[N_NODESC * 64];   // x @ [W1l | W1r]
__device__ float g_h [N_NODESC * 32];   // relu(layer1)
__device__ __nv_bfloat16 g_wh[64 * 256];  // pre-split combined W1 (hi)
__device__ __nv_bfloat16 g_wl[64 * 256];  // pre-split combined W1 (lo)
__device__ int   g_deg[N_NODESC];
__device__ int   g_pos[N_NODESC];
__device__ int   g_off[N_NODESC];       // block-local exclusive scan of deg
__device__ int   g_bsum[128];
__device__ int   g_boff[128];           // exclusive scan of block sums
__device__ int   g_csr[N_EDGESC];
__device__ int   g_tick;                // last-block ticket (reset each run)

// ---------------- packed f32x2 helpers (Blackwell) ----------------
__device__ __forceinline__ unsigned long long ffma2(unsigned long long a, unsigned long long b,
                                                    unsigned long long c) {
    unsigned long long d;
    asm("fma.rn.f32x2 %0, %1, %2, %3;" : "=l"(d) : "l"(a), "l"(b), "l"(c));
    return d;
}

__device__ __forceinline__ uint32_t smem_u32(const void* p) {
    uint32_t a;
    asm("{ .reg .u64 t; cvta.to.shared.u64 t, %1; cvt.u32.u64 %0, t; }" : "=r"(a) : "l"(p));
    return a;
}

// ---------------- CSR build ----------------
__global__ void k_zero() {
    int i = blockIdx.x * blockDim.x + threadIdx.x;
    if (i < N_NODESC) { g_deg[i] = 0; g_pos[i] = 0; }
}

__global__ void k_deg(const int* __restrict__ ei) {
    int i = blockIdx.x * blockDim.x + threadIdx.x;
    if (i < N_EDGESC / 4) {
        int4 d4 = ((const int4*)(ei + N_EDGESC))[i];
        if ((unsigned)d4.x < (unsigned)N_NODESC) atomicAdd(&g_deg[d4.x], 1);
        if ((unsigned)d4.y < (unsigned)N_NODESC) atomicAdd(&g_deg[d4.y], 1);
        if ((unsigned)d4.z < (unsigned)N_NODESC) atomicAdd(&g_deg[d4.z], 1);
        if ((unsigned)d4.w < (unsigned)N_NODESC) atomicAdd(&g_deg[d4.w], 1);
    }
}

__device__ __forceinline__ int warp_iscan(int v) {
    #pragma unroll
    for (int o = 1; o < 32; o <<= 1) {
        int t = __shfl_up_sync(0xffffffffu, v, o);
        if ((threadIdx.x & 31) >= o) v += t;
    }
    return v;
}

__global__ void k_scanF() {
    __shared__ int ws[32];
    __shared__ bool lastf;
    int i = blockIdx.x * 1024 + threadIdx.x;
    int v = (i < N_NODESC) ? g_deg[i] : 0;
    int inc = warp_iscan(v);
    int wid = threadIdx.x >> 5, lane = threadIdx.x & 31;
    if (lane == 31) ws[wid] = inc;
    __syncthreads();
    if (wid == 0) {
        int wv = ws[lane];
        int wi = warp_iscan(wv);
        ws[lane] = wi - wv;
    }
    __syncthreads();
    int excl = inc - v + ws[wid];
    if (i < N_NODESC) g_off[i] = excl;
    if (threadIdx.x == 1023) g_bsum[blockIdx.x] = excl + v;

    __threadfence();
    if (threadIdx.x == 0) lastf = (atomicAdd(&g_tick, 1) == gridDim.x - 1);
    __syncthreads();
    if (lastf && threadIdx.x < 32) {
        int run = 0;
        #pragma unroll
        for (int c = 0; c < 4; c++) {
            int idx = c * 32 + lane;
            int bv = (idx < SCAN_BLKS) ? g_bsum[idx] : 0;
            int binc = warp_iscan(bv);
            if (idx < SCAN_BLKS) g_boff[idx] = run + binc - bv;
            run += __shfl_sync(0xffffffffu, binc, 31);
        }
        if (lane == 0) g_tick = 0;
    }
}

__device__ __forceinline__ int abs_off(int node) {
    return g_off[node] + g_boff[node >> 10];
}

__global__ void k_fill(const int* __restrict__ ei) {
    int i = blockIdx.x * blockDim.x + threadIdx.x;
    if (i < N_EDGESC / 4) {
        int4 s4 = ((const int4*)ei)[i];
        int4 d4 = ((const int4*)(ei + N_EDGESC))[i];
        int s[4] = {s4.x, s4.y, s4.z, s4.w};
        int d[4] = {d4.x, d4.y, d4.z, d4.w};
        #pragma unroll
        for (int j = 0; j < 4; j++) {
            if ((unsigned)d[j] < (unsigned)N_NODESC && (unsigned)s[j] < (unsigned)N_NODESC) {
                int p = atomicAdd(&g_pos[d[j]], 1);
                g_csr[abs_off(d[j]) + p] = s[j];
            }
        }
    }
}

// ---------------- W pre-split: combined [n=64][k=256] -> bf16 hi/lo ----------------
__global__ void k_wsplit(const float* __restrict__ W1l, const float* __restrict__ W1r) {
    int idx = blockIdx.x * 256 + threadIdx.x;   // 64 blocks -> 16384
    int n = idx >> 8, k = idx & 255;
    float v = (n < 32) ? W1l[k * 32 + n] : W1r[k * 32 + (n - 32)];
    __nv_bfloat16 h = __float2bfloat16_rn(v);
    __nv_bfloat16 l = __float2bfloat16_rn(v - __bfloat162float(h));
    g_wh[n * 256 + k] = h;
    g_wl[n * 256 + k] = l;
}

// ---------------- GEMM1 (HMMA bf16 split, K-chunk pipelined) ----------------
// CTA 128 rows x 64 cols, K chunked 4 x 64, double-buffered. Row stride 144B
// (ldmatrix conflict-free). 108KB smem -> 2 CTAs/SM, 16 warps.
#define CH_RS   144
#define SZ_X    (128 * CH_RS)               // 18432
#define SZ_W    (64 * CH_RS)                // 9216
#define OFF_XH  0
#define OFF_XL  SZ_X
#define OFF_WH  (2 * SZ_X)
#define OFF_WL  (2 * SZ_X + SZ_W)
#define BUF_SZ  (2 * SZ_X + 2 * SZ_W)       // 55296
#define G1_SMEM (2 * BUF_SZ)                // 110592

__device__ __forceinline__ uint32_t bpack(__nv_bfloat16 a, __nv_bfloat16 b) {
    return (uint32_t)__bfloat16_as_ushort(a) | ((uint32_t)__bfloat16_as_ushort(b) << 16);
}

__device__ __forceinline__ void ldm_x4(uint32_t* r, uint32_t addr) {
    asm volatile("ldmatrix.sync.aligned.m8n8.x4.shared.b16 {%0,%1,%2,%3}, [%4];"
                 : "=r"(r[0]), "=r"(r[1]), "=r"(r[2]), "=r"(r[3]) : "r"(addr));
}

__device__ __forceinline__ void mma16816(float* c, const uint32_t* a, uint32_t b0, uint32_t b1) {
    asm volatile(
        "mma.sync.aligned.m16n8k16.row.col.f32.bf16.bf16.f32 "
        "{%0,%1,%2,%3}, {%4,%5,%6,%7}, {%8,%9}, {%0,%1,%2,%3};"
        : "+f"(c[0]), "+f"(c[1]), "+f"(c[2]), "+f"(c[3])
        : "r"(a[0]), "r"(a[1]), "r"(a[2]), "r"(a[3]), "r"(b0), "r"(b1));
}

__global__ void __launch_bounds__(256, 2) k_gemm1(const float* __restrict__ x) {
    extern __shared__ char smem[];
    uint32_t sb = smem_u32(smem);
    int tid = threadIdx.x, wid = tid >> 5, lane = tid & 31;
    int mbase = blockIdx.x * 128;

    // loader indices: X -> (row = it*16 + xr, k4 = xk4); W -> (n = it*32 + wn, q = wq)
    int xr = tid >> 4, xk4 = tid & 15;
    int wn = tid >> 3, wq = tid & 7;

    float4 xs[8];
    uint4  wsv[2][2];

    // compute-phase addressing (same fragment layout as validated R9)
    uint32_t a_off = (uint32_t)(wid * 16 + (lane & 15)) * CH_RS + (lane >> 4) * 16;
    uint32_t b_off = (uint32_t)((lane & 7) + ((lane >> 4) << 3)) * CH_RS + ((lane >> 3) & 1) * 16;

    float C[8][4];
    #pragma unroll
    for (int j = 0; j < 8; j++)
        #pragma unroll
        for (int i = 0; i < 4; i++) C[j][i] = 0.f;

    // ---- load chunk c into regs
    #define LOAD_CHUNK(c) do {                                                      \
        int kc = (c) * 64;                                                          \
        _Pragma("unroll")                                                           \
        for (int it = 0; it < 8; it++) {                                            \
            int node = mbase + it * 16 + xr;                                        \
            xs[it] = (node < N_NODESC)                                              \
                ? *(const float4*)(x + (size_t)node * F_INC + kc + xk4 * 4)         \
                : make_float4(0.f, 0.f, 0.f, 0.f);                                  \
        }                                                                           \
        _Pragma("unroll")                                                           \
        for (int it = 0; it < 2; it++) {                                            \
            int n = it * 32 + wn;                                                   \
            wsv[0][it] = *(const uint4*)(g_wh + n * 256 + kc + wq * 8);             \
            wsv[1][it] = *(const uint4*)(g_wl + n * 256 + kc + wq * 8);             \
        }                                                                           \
    } while (0)

    // ---- convert + store staged regs into buffer b
    #define STORE_CHUNK(b) do {                                                     \
        char* bs = smem + (b) * BUF_SZ;                                             \
        _Pragma("unroll")                                                           \
        for (int it = 0; it < 8; it++) {                                            \
            int r = it * 16 + xr;                                                   \
            float vv[4] = {xs[it].x, xs[it].y, xs[it].z, xs[it].w};                 \
            __nv_bfloat16 h[4], l[4];                                               \
            _Pragma("unroll")                                                       \
            for (int j = 0; j < 4; j++) {                                           \
                h[j] = __float2bfloat16_rn(vv[j]);                                  \
                l[j] = __float2bfloat16_rn(vv[j] - __bfloat162float(h[j]));         \
            }                                                                       \
            uint32_t off = r * CH_RS + xk4 * 8;                                     \
            *(uint2*)(bs + OFF_XH + off) = make_uint2(bpack(h[0], h[1]), bpack(h[2], h[3])); \
            *(uint2*)(bs + OFF_XL + off) = make_uint2(bpack(l[0], l[1]), bpack(l[2], l[3])); \
        }                                                                           \
        _Pragma("unroll")                                                           \
        for (int it = 0; it < 2; it++) {                                            \
            int n = it * 32 + wn;                                                   \
            uint32_t off = n * CH_RS + wq * 16;                                     \
            *(uint4*)(bs + OFF_WH + off) = wsv[0][it];                              \
            *(uint4*)(bs + OFF_WL + off) = wsv[1][it];                              \
        }                                                                           \
    } while (0)

    LOAD_CHUNK(0);
    STORE_CHUNK(0);
    __syncthreads();

    #pragma unroll
    for (int c = 0; c < 4; c++) {
        if (c < 3) LOAD_CHUNK(c + 1);

        uint32_t bb = sb + (c & 1) * BUF_SZ;
        uint32_t aH = bb + OFF_XH + a_off;
        uint32_t aL = bb + OFF_XL + a_off;
        uint32_t bH = bb + OFF_WH + b_off;
        uint32_t bL = bb + OFF_WL + b_off;
        #pragma unroll
        for (int ks = 0; ks < 4; ks++) {
            uint32_t koff = ks * 32;
            uint32_t Ah[4], Al[4];
            ldm_x4(Ah, aH + koff);
            ldm_x4(Al, aL + koff);
            #pragma unroll
            for (int nt = 0; nt < 4; nt++) {
                uint32_t Bh[4], Bl[4];
                ldm_x4(Bh, bH + nt * (16 * CH_RS) + koff);
                ldm_x4(Bl, bL + nt * (16 * CH_RS) + koff);
                mma16816(C[2 * nt],     Ah, Bh[0], Bh[1]);
                mma16816(C[2 * nt + 1], Ah, Bh[2], Bh[3]);
                mma16816(C[2 * nt],     Ah, Bl[0], Bl[1]);
                mma16816(C[2 * nt + 1], Ah, Bl[2], Bl[3]);
                mma16816(C[2 * nt],     Al, Bh[0], Bh[1]);
                mma16816(C[2 * nt + 1], Al, Bh[2], Bh[3]);
            }
        }

        if (c < 3) STORE_CHUNK((c + 1) & 1);
        __syncthreads();
    }

    // ---- epilogue: C fragments -> g_p1
    int row0 = wid * 16 + (lane >> 2);
    int cb = (lane & 3) * 2;
    int n0 = mbase + row0;
    int n1 = n0 + 8;
    #pragma unroll
    for (int j = 0; j < 8; j++) {
        int col = (j >> 1) * 16 + (j & 1) * 8 + cb;
        if (n0 < N_NODESC) *(float2*)&g_p1[(size_t)n0 * 64 + col] = make_float2(C[j][0], C[j][1]);
        if (n1 < N_NODESC) *(float2*)&g_p1[(size_t)n1 * 64 + col] = make_float2(C[j][2], C[j][3]);
    }
}

// ---------------- agg1 + combine + relu: warp per node, MLP 8 ----------------
__global__ void __launch_bounds__(256) k_agg1(const float* __restrict__ b1) {
    int w = (blockIdx.x * 256 + threadIdx.x) >> 5;
    int lane = threadIdx.x & 31;
    int deg = g_deg[w];
    int beg = abs_off(w);
    int end = beg + deg;
    float a0 = 0.f, a1 = 0.f, a2 = 0.f, a3 = 0.f;
    int e = beg;
    int e8 = beg + (deg & ~7);
    for (; e < e8; e += 8) {
        int s0 = g_csr[e],     s1 = g_csr[e + 1], s2 = g_csr[e + 2], s3 = g_csr[e + 3];
        int s4 = g_csr[e + 4], s5 = g_csr[e + 5], s6 = g_csr[e + 6], s7 = g_csr[e + 7];
        a0 += g_p1[s0 * 64 + lane];
        a1 += g_p1[s1 * 64 + lane];
        a2 += g_p1[s2 * 64 + lane];
        a3 += g_p1[s3 * 64 + lane];
        a0 += g_p1[s4 * 64 + lane];
        a1 += g_p1[s5 * 64 + lane];
        a2 += g_p1[s6 * 64 + lane];
        a3 += g_p1[s7 * 64 + lane];
    }
    for (; e < end; e++) a0 += g_p1[g_csr[e] * 64 + lane];
    float acc = (a0 + a1) + (a2 + a3);
    float invd = 1.f / fmaxf((float)deg, 1.f);
    float v = acc * invd + g_p1[w * 64 + 32 + lane] + b1[lane];
    g_h[w * 32 + lane] = fmaxf(v, 0.f);
}

// ---------------- final: gather-mean h + [W2l|W2r] matvec + log_softmax ----------------
__global__ void __launch_bounds__(256) k_final(const float* __restrict__ W2l,
                                               const float* __restrict__ W2r,
                                               const float* __restrict__ b2,
                                               float* __restrict__ out) {
    __shared__ float vs[32 * 68];
    __shared__ float Wt[40 * 68];
    __shared__ float b2s[40];
    int tid = threadIdx.x;

    for (int idx = tid; idx < 40 * 64; idx += 256) {
        int c = idx >> 6, k = idx & 63;
        Wt[c * 68 + k] = (k < 32) ? W2l[k * 40 + c] : W2r[(k - 32) * 40 + c];
    }
    if (tid < 40) b2s[tid] = b2[tid];

    int base = blockIdx.x * 32;
    int wid = tid >> 5, lane = tid & 31;

    #pragma unroll
    for (int j = 0; j < 4; j++) {
        int ln = wid * 4 + j;
        int g = base + ln;
        int deg = g_deg[g];
        int beg = abs_off(g);
        int end = beg + deg;
        float a0 = 0.f, a1 = 0.f, a2 = 0.f, a3 = 0.f;
        int e = beg;
        int e8 = beg + (deg & ~7);
        for (; e < e8; e += 8) {
            int s0 = g_csr[e],     s1 = g_csr[e + 1], s2 = g_csr[e + 2], s3 = g_csr[e + 3];
            int s4 = g_csr[e + 4], s5 = g_csr[e + 5], s6 = g_csr[e + 6], s7 = g_csr[e + 7];
            a0 += g_h[s0 * 32 + lane];
            a1 += g_h[s1 * 32 + lane];
            a2 += g_h[s2 * 32 + lane];
            a3 += g_h[s3 * 32 + lane];
            a0 += g_h[s4 * 32 + lane];
            a1 += g_h[s5 * 32 + lane];
            a2 += g_h[s6 * 32 + lane];
            a3 += g_h[s7 * 32 + lane];
        }
        for (; e < end; e++) a0 += g_h[g_csr[e] * 32 + lane];
        float acc = (a0 + a1) + (a2 + a3);
        float invd = 1.f / fmaxf((float)deg, 1.f);
        vs[ln * 68 + lane] = acc * invd;
        vs[ln * 68 + 32 + lane] = g_h[g * 32 + lane];
    }
    __syncthreads();

    int node = tid >> 3, sub = tid & 7, c0 = sub * 5;
    unsigned long long acc[5];
    #pragma unroll
    for (int j = 0; j < 5; j++) acc[j] = 0ull;
    #pragma unroll
    for (int kk = 0; kk < 64; kk += 4) {
        ulonglong2 v = *(const ulonglong2*)&vs[node * 68 + kk];
        #pragma unroll
        for (int j = 0; j < 5; j++) {
            ulonglong2 w = *(const ulonglong2*)&Wt[(c0 + j) * 68 + kk];
            acc[j] = ffma2(v.x, w.x, acc[j]);
            acc[j] = ffma2(v.y, w.y, acc[j]);
        }
    }
    float z[5];
    #pragma unroll
    for (int j = 0; j < 5; j++)
        z[j] = __uint_as_float((unsigned)acc[j]) +
               __uint_as_float((unsigned)(acc[j] >> 32)) + b2s[c0 + j];

    float m = z[0];
    #pragma unroll
    for (int j = 1; j < 5; j++) m = fmaxf(m, z[j]);
    #pragma unroll
    for (int o = 1; o < 8; o <<= 1) m = fmaxf(m, __shfl_xor_sync(0xffffffffu, m, o));
    float s = 0.f;
    #pragma unroll
    for (int j = 0; j < 5; j++) s += expf(z[j] - m);
    #pragma unroll
    for (int o = 1; o < 8; o <<= 1) s += __shfl_xor_sync(0xffffffffu, s, o);
    float ls = logf(s);

    int g = base + node;
    #pragma unroll
    for (int j = 0; j < 5; j++) out[g * 40 + c0 + j] = z[j] - m - ls;
}

// ---------------- launch ----------------
extern "C" void kernel_launch(void* const* d_in, const int* in_sizes, int n_in,
                              void* d_out, int out_size) {
    const float* x   = (const float*)d_in[0];
    const int*   ei  = (const int*)d_in[1];     // int32 (JAX x64 disabled)
    const float* W1l = (const float*)d_in[2];
    const float* W1r = (const float*)d_in[3];
    const float* b1  = (const float*)d_in[4];
    const float* W2l = (const float*)d_in[5];
    const float* W2r = (const float*)d_in[6];
    const float* b2  = (const float*)d_in[7];
    float* out = (float*)d_out;

    static cudaStream_t s1 = nullptr;
    static cudaEvent_t evf = nullptr, evj = nullptr;
    if (s1 == nullptr) {
        cudaStreamCreateWithFlags(&s1, cudaStreamNonBlocking);
        cudaEventCreateWithFlags(&evf, cudaEventDisableTiming);
        cudaEventCreateWithFlags(&evj, cudaEventDisableTiming);
        cudaFuncSetAttribute(k_gemm1, cudaFuncAttributeMaxDynamicSharedMemorySize, G1_SMEM);
    }

    // fork point; side stream does wsplit -> gemm1 concurrent with the CSR chain
    cudaEventRecord(evf, 0);
    cudaStreamWaitEvent(s1, evf, 0);

    k_zero<<<(N_NODESC + 511) / 512, 512>>>();                     // launch 1
    k_deg<<<(N_EDGESC / 4 + 255) / 256, 256>>>(ei);                // launch 2
    k_wsplit<<<64, 256, 0, s1>>>(W1l, W1r);                        // launch 3 (s1)
    k_gemm1<<<(N_NODESC + 127) / 128, 256, G1_SMEM, s1>>>(x);      // launch 4 (profiled, s1)
    cudaEventRecord(evj, s1);
    k_scanF<<<SCAN_BLKS, 1024>>>();                                // launch 5
    k_fill<<<(N_EDGESC / 4 + 255) / 256, 256>>>(ei);               // launch 6

    // join, then layer 1 aggregation and fused layer 2
    cudaStreamWaitEvent(0, evj, 0);
    k_agg1<<<N_NODESC / 8, 256>>>(b1);                             // launch 7
    k_final<<<N_NODESC / 32, 256>>>(W2l, W2r, b2, out);            // launch 8
}